// round 12
// baseline (speedup 1.0000x reference)
#include <cuda_runtime.h>

#define NN 500000
#define NE 8000000
#define TPB 256

// ---------------- scratch (static __device__ — no allocation) ----------------
__device__ float  g_degf[NN];
__device__ float  g_dsr [NN];     // (deg+1)^-1/2
__device__ float  g_dinv[NN];     // (deg+1)^-1
__device__ float2 g_s  [NN];      // current pre-scaled pair s_k = dsr * (u_k, v_k)
__device__ float2 g_a0 [NN];      // pass-k accumulators  a_k = (A+I) s_k
__device__ float2 g_a1 [NN];
__device__ float2 g_a2 [NN];
__device__ float2 g_a3 [NN];
__device__ float  g_R  [128];     // R1,R2,R3,R4 (each 32) — collapsed weight rows

// ---------------- weights in constant memory ----------------
// layout: W1[4] b1[4] W2[32] b2[8] W3[128] b3[16] W4[512] b4[32] = 736 floats
__constant__ float c_w[736];
#define W1_OFF 0
#define B1_OFF 4
#define W2_OFF 8
#define B2_OFF 40
#define W3_OFF 48
#define B3_OFF 176
#define W4_OFF 192
#define B4_OFF 704

// ---------------- reductions ----------------
__device__ __forceinline__ void red_add(float* a, float v) {
    asm volatile("red.global.add.f32 [%0], %1;" :: "l"(a), "f"(v) : "memory");
}
__device__ __forceinline__ void red_add2(float* a, float2 v) {
    asm volatile("red.global.add.v2.f32 [%0], {%1, %2};"
                 :: "l"(a), "f"(v.x), "f"(v.y) : "memory");
}

// Compile-time accumulator selection — device-side symbol references only.
// (R8 bug: passing __device__ arrays as host-side kernel args yields the host
// shadow address, not the device address.)
template<int K> __device__ __forceinline__ float2* acc_ptr() {
    if (K == 0) return g_a0;
    if (K == 1) return g_a1;
    if (K == 2) return g_a2;
    return g_a3;
}

// ---------------- kernels ----------------
__global__ void k_zero() {
    int i = blockIdx.x * TPB + threadIdx.x;
    if (i < NN) g_degf[i] = 0.f;
}

__global__ void k_deg(const int* __restrict__ dst) {
    int e = blockIdx.x * TPB + threadIdx.x;
    if (e < NE) red_add(&g_degf[dst[e]], 1.0f);
}

// Collapse the weight chain into 4 rank-1 coefficient rows (1 warp).
// R1 = W1W2W3W4 ; R2 = b1W2W3W4 ; R3 = b2W3W4 ; R4 = b3W4
__global__ void k_prep() {
    int j = threadIdx.x;
    if (j >= 32) return;
    float c8[8], c16[16];

    // R1 chain: W1 (1x4) -> 8 -> 16 -> col j of 32
#pragma unroll
    for (int m = 0; m < 8; m++) {
        float t = 0.f;
#pragma unroll
        for (int k = 0; k < 4; k++) t = fmaf(c_w[W1_OFF + k], c_w[W2_OFF + k * 8 + m], t);
        c8[m] = t;
    }
#pragma unroll
    for (int n = 0; n < 16; n++) {
        float t = 0.f;
#pragma unroll
        for (int m = 0; m < 8; m++) t = fmaf(c8[m], c_w[W3_OFF + m * 16 + n], t);
        c16[n] = t;
    }
    {
        float t = 0.f;
#pragma unroll
        for (int n = 0; n < 16; n++) t = fmaf(c16[n], c_w[W4_OFF + n * 32 + j], t);
        g_R[j] = t;
    }

    // R2 chain: b1 -> 8 -> 16 -> j
#pragma unroll
    for (int m = 0; m < 8; m++) {
        float t = 0.f;
#pragma unroll
        for (int k = 0; k < 4; k++) t = fmaf(c_w[B1_OFF + k], c_w[W2_OFF + k * 8 + m], t);
        c8[m] = t;
    }
#pragma unroll
    for (int n = 0; n < 16; n++) {
        float t = 0.f;
#pragma unroll
        for (int m = 0; m < 8; m++) t = fmaf(c8[m], c_w[W3_OFF + m * 16 + n], t);
        c16[n] = t;
    }
    {
        float t = 0.f;
#pragma unroll
        for (int n = 0; n < 16; n++) t = fmaf(c16[n], c_w[W4_OFF + n * 32 + j], t);
        g_R[32 + j] = t;
    }

    // R3 chain: b2 (8) -> 16 -> j
#pragma unroll
    for (int n = 0; n < 16; n++) {
        float t = 0.f;
#pragma unroll
        for (int m = 0; m < 8; m++) t = fmaf(c_w[B2_OFF + m], c_w[W3_OFF + m * 16 + n], t);
        c16[n] = t;
    }
    {
        float t = 0.f;
#pragma unroll
        for (int n = 0; n < 16; n++) t = fmaf(c16[n], c_w[W4_OFF + n * 32 + j], t);
        g_R[64 + j] = t;
    }

    // R4: b3 (16) @ W4 -> j
    {
        float t = 0.f;
#pragma unroll
        for (int n = 0; n < 16; n++) t = fmaf(c_w[B3_OFF + n], c_w[W4_OFF + n * 32 + j], t);
        g_R[96 + j] = t;
    }
}

// deg -> dsr,dinv ; s0 = dsr*(x, 1) ; a0 = s0 (self term folded in)
__global__ void k_node1(const int* __restrict__ rl) {
    int i = blockIdx.x * TPB + threadIdx.x;
    if (i >= NN) return;
    float deg = g_degf[i] + 1.0f;
    float ds  = rsqrtf(deg);
    float di  = 1.0f / deg;
    g_dsr[i]  = ds;
    g_dinv[i] = di;
    float2 s  = make_float2((float)rl[i] * (1.0f / 20000.0f) * ds, ds);
    g_s[i]  = s;
    g_a0[i] = s;
}

// F=2 edge pass K: pure gather + RED.v2 into a_K
template<int K>
__global__ void k_edge(const int* __restrict__ src, const int* __restrict__ dst) {
    int e = blockIdx.x * TPB + threadIdx.x;
    if (e >= NE) return;
    float2 v = g_s[src[e]];
    red_add2((float*)(acc_ptr<K>() + dst[e]), v);
}

// between passes: s_{k+1} = dinv * a_k ; a_{k+1} = s_{k+1}
template<int K>
__global__ void k_mid() {
    int i = blockIdx.x * TPB + threadIdx.x;
    if (i >= NN) return;
    float di = g_dinv[i];
    float2 v = acc_ptr<K>()[i];
    float2 s = make_float2(di * v.x, di * v.y);
    g_s[i]             = s;
    acc_ptr<K + 1>()[i] = s;
}

// out[i][:] = u4*R1 + v3*R2 + v2*R3 + v1*R4 + b4
__global__ void k_out(float* __restrict__ out) {
    int i = blockIdx.x * TPB + threadIdx.x;
    if (i >= NN) return;
    float ds = g_dsr[i];
    float u4 = ds * g_a3[i].x;
    float v3 = ds * g_a2[i].y;
    float v2 = ds * g_a1[i].y;
    float v1 = ds * g_a0[i].y;
    float4* o = (float4*)(out + (size_t)i * 32);
#pragma unroll
    for (int c = 0; c < 8; c++) {
        float4 r;
        float* rp = (float*)&r;
#pragma unroll
        for (int q = 0; q < 4; q++) {
            int j = 4 * c + q;
            float t = c_w[B4_OFF + j];
            t = fmaf(u4, g_R[j],      t);
            t = fmaf(v3, g_R[32 + j], t);
            t = fmaf(v2, g_R[64 + j], t);
            t = fmaf(v1, g_R[96 + j], t);
            rp[q] = t;
        }
        o[c] = r;
    }
}

// ---------------- launch ----------------
extern "C" void kernel_launch(void* const* d_in, const int* in_sizes, int n_in,
                              void* d_out, int out_size) {
    const int* rl  = (const int*)d_in[0];
    const int* ei  = (const int*)d_in[1];
    const int* src = ei;
    const int* dst = ei + NE;

    cudaMemcpyToSymbolAsync(c_w, d_in[2],   4 * sizeof(float), W1_OFF * sizeof(float), cudaMemcpyDeviceToDevice, 0);
    cudaMemcpyToSymbolAsync(c_w, d_in[3],   4 * sizeof(float), B1_OFF * sizeof(float), cudaMemcpyDeviceToDevice, 0);
    cudaMemcpyToSymbolAsync(c_w, d_in[4],  32 * sizeof(float), W2_OFF * sizeof(float), cudaMemcpyDeviceToDevice, 0);
    cudaMemcpyToSymbolAsync(c_w, d_in[5],   8 * sizeof(float), B2_OFF * sizeof(float), cudaMemcpyDeviceToDevice, 0);
    cudaMemcpyToSymbolAsync(c_w, d_in[6], 128 * sizeof(float), W3_OFF * sizeof(float), cudaMemcpyDeviceToDevice, 0);
    cudaMemcpyToSymbolAsync(c_w, d_in[7],  16 * sizeof(float), B3_OFF * sizeof(float), cudaMemcpyDeviceToDevice, 0);
    cudaMemcpyToSymbolAsync(c_w, d_in[8], 512 * sizeof(float), W4_OFF * sizeof(float), cudaMemcpyDeviceToDevice, 0);
    cudaMemcpyToSymbolAsync(c_w, d_in[9],  32 * sizeof(float), B4_OFF * sizeof(float), cudaMemcpyDeviceToDevice, 0);

    const int nb_n = (NN + TPB - 1) / TPB;
    const int nb_e = (NE + TPB - 1) / TPB;

    k_prep   <<<1,    32 >>>();
    k_zero   <<<nb_n, TPB>>>();
    k_deg    <<<nb_e, TPB>>>(dst);
    k_node1  <<<nb_n, TPB>>>(rl);
    k_edge<0><<<nb_e, TPB>>>(src, dst);
    k_mid<0> <<<nb_n, TPB>>>();
    k_edge<1><<<nb_e, TPB>>>(src, dst);
    k_mid<1> <<<nb_n, TPB>>>();
    k_edge<2><<<nb_e, TPB>>>(src, dst);
    k_mid<2> <<<nb_n, TPB>>>();
    k_edge<3><<<nb_e, TPB>>>(src, dst);
    k_out    <<<nb_n, TPB>>>((float*)d_out);
}

// round 14
// speedup vs baseline: 1.7429x; 1.7429x over previous
#include <cuda_runtime.h>

#define NN 500000
#define NE 8000000
#define TPB 256
#define NB_N ((NN + TPB - 1) / TPB)   // 1954 node blocks

// ---------------- scratch (static __device__ — no allocation) ----------------
__device__ int    g_hist[NN];      // in-degree (no self loop)
__device__ int    g_excl[NN];      // exclusive scan within block
__device__ int    g_bsum[2048];    // per-block sums
__device__ int    g_boff[2048];    // exclusive-scanned block offsets
__device__ int    g_row [NN];      // CSR row starts
__device__ int    g_cur [NN];      // scatter cursors
__device__ int    g_csr [NE];      // src indices grouped by dst
__device__ float  g_dinv[NN];      // 1/(deg+1)
__device__ float  g_sqd [NN];      // sqrt(deg+1)
__device__ float2 g_s0[NN], g_s1[NN], g_s2[NN], g_s3[NN], g_s4[NN]; // s_k = dsr*(u_k, v_k)
__device__ float  g_R  [128];      // R1,R2,R3,R4 (each 32) — collapsed weight rows

// ---------------- weights in constant memory ----------------
__constant__ float c_w[736];
#define W1_OFF 0
#define B1_OFF 4
#define W2_OFF 8
#define B2_OFF 40
#define W3_OFF 48
#define B3_OFF 176
#define W4_OFF 192
#define B4_OFF 704

// Compile-time s_k selection (device-side symbol refs only — R8 lesson).
template<int K> __device__ __forceinline__ float2* s_ptr() {
    if (K == 0) return g_s0;
    if (K == 1) return g_s1;
    if (K == 2) return g_s2;
    if (K == 3) return g_s3;
    return g_s4;
}

// ---------------- kernels ----------------
__global__ void k_zero() {
    int i = blockIdx.x * TPB + threadIdx.x;
    if (i < NN) g_hist[i] = 0;
}

__global__ void k_deg(const int* __restrict__ dst) {
    int e = blockIdx.x * TPB + threadIdx.x;
    if (e < NE) atomicAdd(&g_hist[dst[e]], 1);   // no return use -> RED
}

// block-wise exclusive scan of g_hist
__global__ void k_scan1() {
    __shared__ int bufA[TPB], bufB[TPB];
    int t = threadIdx.x;
    int i = blockIdx.x * TPB + t;
    bufA[t] = (i < NN) ? g_hist[i] : 0;
    __syncthreads();
    int* in = bufA; int* out = bufB;
#pragma unroll
    for (int off = 1; off < TPB; off <<= 1) {
        out[t] = in[t] + (t >= off ? in[t - off] : 0);
        __syncthreads();
        int* tmp = in; in = out; out = tmp;
    }
    if (i < NN) g_excl[i] = (t ? in[t - 1] : 0);
    if (t == TPB - 1) g_bsum[blockIdx.x] = in[t];
}

// single-block exclusive scan of 1954 block sums (padded to 2048)
__global__ void k_scan2() {
    __shared__ int bufA[2048], bufB[2048];
    int t = threadIdx.x;                      // 1024 threads
    for (int k = t; k < 2048; k += 1024) bufA[k] = (k < NB_N) ? g_bsum[k] : 0;
    __syncthreads();
    int* in = bufA; int* out = bufB;
#pragma unroll
    for (int off = 1; off < 2048; off <<= 1) {
        for (int k = t; k < 2048; k += 1024)
            out[k] = in[k] + (k >= off ? in[k - off] : 0);
        __syncthreads();
        int* tmp = in; in = out; out = tmp;
    }
    for (int k = t; k < NB_N; k += 1024) g_boff[k] = (k ? in[k - 1] : 0);
}

// row starts + cursors + degree terms + s0 ; fuses scan level-3
__global__ void k_node1(const int* __restrict__ rl) {
    int i = blockIdx.x * TPB + threadIdx.x;
    if (i >= NN) return;
    int row = g_excl[i] + g_boff[blockIdx.x];
    g_row[i] = row;
    g_cur[i] = row;
    float deg = (float)g_hist[i] + 1.0f;
    float ds  = rsqrtf(deg);
    g_dinv[i] = 1.0f / deg;
    g_sqd[i]  = sqrtf(deg);
    g_s0[i]   = make_float2((float)rl[i] * (1.0f / 20000.0f) * ds, ds);
}

// counting-sort scatter: group src indices by dst
__global__ void k_scatter(const int* __restrict__ src, const int* __restrict__ dst) {
    int e = blockIdx.x * TPB + threadIdx.x;
    if (e >= NE) return;
    int p = atomicAdd(&g_cur[dst[e]], 1);
    g_csr[p] = src[e];
}

// pull pass K: s_{K+1}[i] = dinv_i * (s_K[i] + sum_{j->i} s_K[j])  — no atomics
template<int K>
__global__ void k_pull() {
    int i = blockIdx.x * TPB + threadIdx.x;
    if (i >= NN) return;
    const float2* __restrict__ s = s_ptr<K>();
    int beg = g_row[i];
    int end = beg + g_hist[i];
    float2 self = s[i];
    float ax = self.x, ay = self.y;
    float bx = 0.f, by = 0.f;
    int j = beg;
    for (; j + 1 < end; j += 2) {                 // 2-way MLP
        int n0 = g_csr[j], n1 = g_csr[j + 1];
        float2 v0 = s[n0], v1 = s[n1];
        ax += v0.x; ay += v0.y;
        bx += v1.x; by += v1.y;
    }
    if (j < end) {
        float2 v = s[g_csr[j]];
        ax += v.x; ay += v.y;
    }
    float di = g_dinv[i];
    s_ptr<K + 1>()[i] = make_float2(di * (ax + bx), di * (ay + by));
}

// Collapse the weight chain into 4 rank-1 coefficient rows (1 warp).
// R1 = W1W2W3W4 ; R2 = b1W2W3W4 ; R3 = b2W3W4 ; R4 = b3W4   (verified in R12)
__global__ void k_prep() {
    int j = threadIdx.x;
    if (j >= 32) return;
    float c8[8], c16[16];
#pragma unroll
    for (int m = 0; m < 8; m++) {
        float t = 0.f;
#pragma unroll
        for (int k = 0; k < 4; k++) t = fmaf(c_w[W1_OFF + k], c_w[W2_OFF + k * 8 + m], t);
        c8[m] = t;
    }
#pragma unroll
    for (int n = 0; n < 16; n++) {
        float t = 0.f;
#pragma unroll
        for (int m = 0; m < 8; m++) t = fmaf(c8[m], c_w[W3_OFF + m * 16 + n], t);
        c16[n] = t;
    }
    {
        float t = 0.f;
#pragma unroll
        for (int n = 0; n < 16; n++) t = fmaf(c16[n], c_w[W4_OFF + n * 32 + j], t);
        g_R[j] = t;
    }
#pragma unroll
    for (int m = 0; m < 8; m++) {
        float t = 0.f;
#pragma unroll
        for (int k = 0; k < 4; k++) t = fmaf(c_w[B1_OFF + k], c_w[W2_OFF + k * 8 + m], t);
        c8[m] = t;
    }
#pragma unroll
    for (int n = 0; n < 16; n++) {
        float t = 0.f;
#pragma unroll
        for (int m = 0; m < 8; m++) t = fmaf(c8[m], c_w[W3_OFF + m * 16 + n], t);
        c16[n] = t;
    }
    {
        float t = 0.f;
#pragma unroll
        for (int n = 0; n < 16; n++) t = fmaf(c16[n], c_w[W4_OFF + n * 32 + j], t);
        g_R[32 + j] = t;
    }
#pragma unroll
    for (int n = 0; n < 16; n++) {
        float t = 0.f;
#pragma unroll
        for (int m = 0; m < 8; m++) t = fmaf(c_w[B2_OFF + m], c_w[W3_OFF + m * 16 + n], t);
        c16[n] = t;
    }
    {
        float t = 0.f;
#pragma unroll
        for (int n = 0; n < 16; n++) t = fmaf(c16[n], c_w[W4_OFF + n * 32 + j], t);
        g_R[64 + j] = t;
    }
    {
        float t = 0.f;
#pragma unroll
        for (int n = 0; n < 16; n++) t = fmaf(c_w[B3_OFF + n], c_w[W4_OFF + n * 32 + j], t);
        g_R[96 + j] = t;
    }
}

// out[i][:] = t4.u*R1 + t3.v*R2 + t2.v*R3 + t1.v*R4 + b4 ; t_k = sqd * s_k
__global__ void k_out(float* __restrict__ out) {
    int i = blockIdx.x * TPB + threadIdx.x;
    if (i >= NN) return;
    float q  = g_sqd[i];
    float u4 = q * g_s4[i].x;
    float v3 = q * g_s3[i].y;
    float v2 = q * g_s2[i].y;
    float v1 = q * g_s1[i].y;
    float4* o = (float4*)(out + (size_t)i * 32);
#pragma unroll
    for (int c = 0; c < 8; c++) {
        float4 r;
        float* rp = (float*)&r;
#pragma unroll
        for (int qq = 0; qq < 4; qq++) {
            int j = 4 * c + qq;
            float t = c_w[B4_OFF + j];
            t = fmaf(u4, g_R[j],      t);
            t = fmaf(v3, g_R[32 + j], t);
            t = fmaf(v2, g_R[64 + j], t);
            t = fmaf(v1, g_R[96 + j], t);
            rp[qq] = t;
        }
        o[c] = r;
    }
}

// ---------------- launch ----------------
extern "C" void kernel_launch(void* const* d_in, const int* in_sizes, int n_in,
                              void* d_out, int out_size) {
    const int* rl  = (const int*)d_in[0];
    const int* ei  = (const int*)d_in[1];
    const int* src = ei;
    const int* dst = ei + NE;

    cudaMemcpyToSymbolAsync(c_w, d_in[2],   4 * sizeof(float), W1_OFF * sizeof(float), cudaMemcpyDeviceToDevice, 0);
    cudaMemcpyToSymbolAsync(c_w, d_in[3],   4 * sizeof(float), B1_OFF * sizeof(float), cudaMemcpyDeviceToDevice, 0);
    cudaMemcpyToSymbolAsync(c_w, d_in[4],  32 * sizeof(float), W2_OFF * sizeof(float), cudaMemcpyDeviceToDevice, 0);
    cudaMemcpyToSymbolAsync(c_w, d_in[5],   8 * sizeof(float), B2_OFF * sizeof(float), cudaMemcpyDeviceToDevice, 0);
    cudaMemcpyToSymbolAsync(c_w, d_in[6], 128 * sizeof(float), W3_OFF * sizeof(float), cudaMemcpyDeviceToDevice, 0);
    cudaMemcpyToSymbolAsync(c_w, d_in[7],  16 * sizeof(float), B3_OFF * sizeof(float), cudaMemcpyDeviceToDevice, 0);
    cudaMemcpyToSymbolAsync(c_w, d_in[8], 512 * sizeof(float), W4_OFF * sizeof(float), cudaMemcpyDeviceToDevice, 0);
    cudaMemcpyToSymbolAsync(c_w, d_in[9],  32 * sizeof(float), B4_OFF * sizeof(float), cudaMemcpyDeviceToDevice, 0);

    const int nb_e = (NE + TPB - 1) / TPB;

    k_prep   <<<1,    32  >>>();
    k_zero   <<<NB_N, TPB >>>();
    k_deg    <<<nb_e, TPB >>>(dst);
    k_scan1  <<<NB_N, TPB >>>();
    k_scan2  <<<1,    1024>>>();
    k_node1  <<<NB_N, TPB >>>(rl);
    k_scatter<<<nb_e, TPB >>>(src, dst);
    k_pull<0><<<NB_N, TPB >>>();
    k_pull<1><<<NB_N, TPB >>>();
    k_pull<2><<<NB_N, TPB >>>();
    k_pull<3><<<NB_N, TPB >>>();
    k_out    <<<NB_N, TPB >>>((float*)d_out);
}